// round 1
// baseline (speedup 1.0000x reference)
#include <cuda_runtime.h>

// out[b,t,c] = (1/(t+1)) * sum_{s<=t} x[b,s,c]
// Causal running mean along T: segmented prefix sum per (b,c) column.
// Two-pass chunked scan for parallelism over T.

#define BB 4
#define TT 4096
#define CC 1024
#define NCHUNK 32
#define CHUNK_T (TT / NCHUNK)   // 128
#define CTILE 256               // threads per block, columns per block

// Scratch: per-(b,chunk,c) partial sums. 4*32*1024*4 = 512 KB.
__device__ float g_partials[BB * NCHUNK * CC];

__global__ void __launch_bounds__(CTILE)
pass1_chunk_sums(const float* __restrict__ x) {
    const int c     = blockIdx.x * CTILE + threadIdx.x;
    const int chunk = blockIdx.y;
    const int b     = blockIdx.z;

    const float* p = x + ((size_t)b * TT + (size_t)chunk * CHUNK_T) * CC + c;

    float acc = 0.0f;
#pragma unroll 8
    for (int t = 0; t < CHUNK_T; ++t) {
        acc += p[(size_t)t * CC];
    }
    g_partials[(b * NCHUNK + chunk) * CC + c] = acc;
}

__global__ void __launch_bounds__(CTILE)
pass2_scan(const float* __restrict__ x, float* __restrict__ out) {
    const int c     = blockIdx.x * CTILE + threadIdx.x;
    const int chunk = blockIdx.y;
    const int b     = blockIdx.z;

    // Exclusive prefix of chunk sums for this column (<= 31 loads, L2-resident).
    float offset = 0.0f;
    const float* part = &g_partials[b * NCHUNK * CC + c];
    for (int k = 0; k < chunk; ++k) {
        offset += part[(size_t)k * CC];
    }

    const size_t base = ((size_t)b * TT + (size_t)chunk * CHUNK_T) * CC + c;
    const float* p = x + base;
    float*       q = out + base;

    const int t0 = chunk * CHUNK_T;
    float acc = offset;
#pragma unroll 4
    for (int t = 0; t < CHUNK_T; ++t) {
        acc += p[(size_t)t * CC];
        q[(size_t)t * CC] = acc * __fdividef(1.0f, (float)(t0 + t + 1));
    }
}

extern "C" void kernel_launch(void* const* d_in, const int* in_sizes, int n_in,
                              void* d_out, int out_size) {
    const float* x = (const float*)d_in[0];
    float* out = (float*)d_out;

    dim3 grid(CC / CTILE, NCHUNK, BB);   // (4, 32, 4) = 512 blocks
    dim3 block(CTILE);

    pass1_chunk_sums<<<grid, block>>>(x);
    pass2_scan<<<grid, block>>>(x, out);
}

// round 2
// speedup vs baseline: 1.0618x; 1.0618x over previous
#include <cuda_runtime.h>

// out[b,t,c] = (1/(t+1)) * sum_{s<=t} x[b,s,c]
// Causal running mean along T. Two-pass chunked scan, float4-vectorized.

#define BB 4
#define TT 4096
#define CC 1024
#define NCHUNK 64
#define CHUNK_T (TT / NCHUNK)   // 64
#define NTHREADS 256            // 256 threads * float4 = 1024 columns = all of C

// Scratch: per-(b,chunk) chunk sums over all C. 4*64*1024*4B = 1 MB.
__device__ float4 g_partials[BB * NCHUNK * (CC / 4)];

__global__ void __launch_bounds__(NTHREADS)
pass1_chunk_sums(const float* __restrict__ x) {
    const int c4    = threadIdx.x;            // float4 column index 0..255
    const int chunk = blockIdx.y;
    const int b     = blockIdx.z;

    const float4* p = (const float4*)(x + ((size_t)b * TT + (size_t)chunk * CHUNK_T) * CC) + c4;

    // Two accumulators to halve the FADD dependency chain.
    float4 a0 = make_float4(0.f, 0.f, 0.f, 0.f);
    float4 a1 = make_float4(0.f, 0.f, 0.f, 0.f);
#pragma unroll 8
    for (int t = 0; t < CHUNK_T; t += 2) {
        float4 v0 = p[(size_t)t * (CC / 4)];
        float4 v1 = p[(size_t)(t + 1) * (CC / 4)];
        a0.x += v0.x; a0.y += v0.y; a0.z += v0.z; a0.w += v0.w;
        a1.x += v1.x; a1.y += v1.y; a1.z += v1.z; a1.w += v1.w;
    }
    float4 s;
    s.x = a0.x + a1.x; s.y = a0.y + a1.y; s.z = a0.z + a1.z; s.w = a0.w + a1.w;
    g_partials[(b * NCHUNK + chunk) * (CC / 4) + c4] = s;
}

__global__ void __launch_bounds__(NTHREADS)
pass2_scan(const float* __restrict__ x, float* __restrict__ out) {
    const int c4    = threadIdx.x;
    const int chunk = blockIdx.y;
    const int b     = blockIdx.z;

    // Exclusive prefix of chunk sums for this float4 column (<= 63 L2-resident loads).
    float4 off = make_float4(0.f, 0.f, 0.f, 0.f);
    const float4* part = &g_partials[b * NCHUNK * (CC / 4) + c4];
    for (int k = 0; k < chunk; ++k) {
        float4 v = part[(size_t)k * (CC / 4)];
        off.x += v.x; off.y += v.y; off.z += v.z; off.w += v.w;
    }

    const size_t base = ((size_t)b * TT + (size_t)chunk * CHUNK_T) * CC;
    const float4* p = (const float4*)(x + base) + c4;
    float4*       q = (float4*)(out + base) + c4;

    const int t0 = chunk * CHUNK_T;
    float4 acc = off;
#pragma unroll 8
    for (int t = 0; t < CHUNK_T; ++t) {
        float4 v = p[(size_t)t * (CC / 4)];
        acc.x += v.x; acc.y += v.y; acc.z += v.z; acc.w += v.w;
        float inv = __fdividef(1.0f, (float)(t0 + t + 1));
        float4 o;
        o.x = acc.x * inv; o.y = acc.y * inv; o.z = acc.z * inv; o.w = acc.w * inv;
        q[(size_t)t * (CC / 4)] = o;
    }
}

extern "C" void kernel_launch(void* const* d_in, const int* in_sizes, int n_in,
                              void* d_out, int out_size) {
    const float* x = (const float*)d_in[0];
    float* out = (float*)d_out;

    dim3 grid(1, NCHUNK, BB);   // 256 blocks
    dim3 block(NTHREADS);

    pass1_chunk_sums<<<grid, block>>>(x);
    pass2_scan<<<grid, block>>>(x, out);
}

// round 3
// speedup vs baseline: 1.1015x; 1.0374x over previous
#include <cuda_runtime.h>

// out[b,t,c] = (1/(t+1)) * sum_{s<=t} x[b,s,c]
// Causal running mean along T. Two-pass chunked scan, float4-vectorized.

#define BB 4
#define TT 4096
#define CC 1024
#define NCHUNK 64
#define CHUNK_T (TT / NCHUNK)   // 64
#define NTHREADS 256            // 256 threads * float4 = 1024 columns = all of C

// Scratch: per-(b,chunk) chunk sums over all C. 4*64*1024*4B = 1 MB.
__device__ float4 g_partials[BB * NCHUNK * (CC / 4)];

__global__ void __launch_bounds__(NTHREADS)
pass1_chunk_sums(const float* __restrict__ x) {
    const int c4    = threadIdx.x;            // float4 column index 0..255
    const int chunk = blockIdx.y;
    const int b     = blockIdx.z;

    const float4* p = (const float4*)(x + ((size_t)b * TT + (size_t)chunk * CHUNK_T) * CC) + c4;

    // Two accumulators to halve the FADD dependency chain.
    float4 a0 = make_float4(0.f, 0.f, 0.f, 0.f);
    float4 a1 = make_float4(0.f, 0.f, 0.f, 0.f);
#pragma unroll 8
    for (int t = 0; t < CHUNK_T; t += 2) {
        float4 v0 = p[(size_t)t * (CC / 4)];
        float4 v1 = p[(size_t)(t + 1) * (CC / 4)];
        a0.x += v0.x; a0.y += v0.y; a0.z += v0.z; a0.w += v0.w;
        a1.x += v1.x; a1.y += v1.y; a1.z += v1.z; a1.w += v1.w;
    }
    float4 s;
    s.x = a0.x + a1.x; s.y = a0.y + a1.y; s.z = a0.z + a1.z; s.w = a0.w + a1.w;
    g_partials[(b * NCHUNK + chunk) * (CC / 4) + c4] = s;
}

__global__ void __launch_bounds__(NTHREADS)
pass2_scan(const float* __restrict__ x, float* __restrict__ out) {
    const int c4    = threadIdx.x;
    const int chunk = blockIdx.y;
    const int b     = blockIdx.z;

    // Exclusive prefix of chunk sums for this float4 column (<= 63 L2-resident loads).
    float4 off = make_float4(0.f, 0.f, 0.f, 0.f);
    const float4* part = &g_partials[b * NCHUNK * (CC / 4) + c4];
    for (int k = 0; k < chunk; ++k) {
        float4 v = part[(size_t)k * (CC / 4)];
        off.x += v.x; off.y += v.y; off.z += v.z; off.w += v.w;
    }

    const size_t base = ((size_t)b * TT + (size_t)chunk * CHUNK_T) * CC;
    const float4* p = (const float4*)(x + base) + c4;
    float4*       q = (float4*)(out + base) + c4;

    const int t0 = chunk * CHUNK_T;
    float4 acc = off;
#pragma unroll 8
    for (int t = 0; t < CHUNK_T; ++t) {
        float4 v = p[(size_t)t * (CC / 4)];
        acc.x += v.x; acc.y += v.y; acc.z += v.z; acc.w += v.w;
        float inv = __fdividef(1.0f, (float)(t0 + t + 1));
        float4 o;
        o.x = acc.x * inv; o.y = acc.y * inv; o.z = acc.z * inv; o.w = acc.w * inv;
        q[(size_t)t * (CC / 4)] = o;
    }
}

extern "C" void kernel_launch(void* const* d_in, const int* in_sizes, int n_in,
                              void* d_out, int out_size) {
    const float* x = (const float*)d_in[0];
    float* out = (float*)d_out;

    dim3 grid(1, NCHUNK, BB);   // 256 blocks
    dim3 block(NTHREADS);

    pass1_chunk_sums<<<grid, block>>>(x);
    pass2_scan<<<grid, block>>>(x, out);
}

// round 5
// speedup vs baseline: 1.1093x; 1.0071x over previous
#include <cuda_runtime.h>

// out[b,t,c] = (1/(t+1)) * sum_{s<=t} x[b,s,c]
// Causal running mean along T. Two-pass chunked scan, float4-vectorized.
// L2-residency play: pass1 streams x into L2; pass2 reads x via __ldcg (L2)
// and writes out via __stcs (evict-first) so the output stream doesn't evict x.

#define BB 4
#define TT 4096
#define CC 1024
#define NCHUNK 128
#define CHUNK_T (TT / NCHUNK)   // 32
#define NTHREADS 256            // 256 threads * float4 = 1024 columns = all of C

// Scratch: per-(b,chunk) chunk sums over all C. 4*128*1024*4B = 2 MB.
__device__ float4 g_partials[BB * NCHUNK * (CC / 4)];

__global__ void __launch_bounds__(NTHREADS)
pass1_chunk_sums(const float* __restrict__ x) {
    const int c4    = threadIdx.x;            // float4 column index 0..255
    const int chunk = blockIdx.y;
    const int b     = blockIdx.z;

    const float4* p = (const float4*)(x + ((size_t)b * TT + (size_t)chunk * CHUNK_T) * CC) + c4;

    // Two accumulators to halve the FADD dependency chain.
    float4 a0 = make_float4(0.f, 0.f, 0.f, 0.f);
    float4 a1 = make_float4(0.f, 0.f, 0.f, 0.f);
#pragma unroll 8
    for (int t = 0; t < CHUNK_T; t += 2) {
        float4 v0 = p[(size_t)t * (CC / 4)];
        float4 v1 = p[(size_t)(t + 1) * (CC / 4)];
        a0.x += v0.x; a0.y += v0.y; a0.z += v0.z; a0.w += v0.w;
        a1.x += v1.x; a1.y += v1.y; a1.z += v1.z; a1.w += v1.w;
    }
    float4 s;
    s.x = a0.x + a1.x; s.y = a0.y + a1.y; s.z = a0.z + a1.z; s.w = a0.w + a1.w;
    g_partials[(b * NCHUNK + chunk) * (CC / 4) + c4] = s;
}

__global__ void __launch_bounds__(NTHREADS)
pass2_scan(const float* __restrict__ x, float* __restrict__ out) {
    const int c4    = threadIdx.x;
    const int chunk = blockIdx.y;
    const int b     = blockIdx.z;

    // Exclusive prefix of chunk sums for this float4 column (L2-resident loads).
    float4 off = make_float4(0.f, 0.f, 0.f, 0.f);
    const float4* part = &g_partials[b * NCHUNK * (CC / 4) + c4];
    for (int k = 0; k < chunk; ++k) {
        float4 v = __ldcg(&part[(size_t)k * (CC / 4)]);
        off.x += v.x; off.y += v.y; off.z += v.z; off.w += v.w;
    }

    const size_t base = ((size_t)b * TT + (size_t)chunk * CHUNK_T) * CC;
    const float4* p = (const float4*)(x + base) + c4;
    float4*       q = (float4*)(out + base) + c4;

    const int t0 = chunk * CHUNK_T;
    float4 acc = off;
#pragma unroll 8
    for (int t = 0; t < CHUNK_T; ++t) {
        float4 v = __ldcg(&p[(size_t)t * (CC / 4)]);   // expect L2 hit (x resident)
        acc.x += v.x; acc.y += v.y; acc.z += v.z; acc.w += v.w;
        float inv = __fdividef(1.0f, (float)(t0 + t + 1));
        float4 o;
        o.x = acc.x * inv; o.y = acc.y * inv; o.z = acc.z * inv; o.w = acc.w * inv;
        __stcs(&q[(size_t)t * (CC / 4)], o);           // evict-first: don't evict x from L2
    }
}

extern "C" void kernel_launch(void* const* d_in, const int* in_sizes, int n_in,
                              void* d_out, int out_size) {
    const float* x = (const float*)d_in[0];
    float* out = (float*)d_out;

    dim3 grid(1, NCHUNK, BB);   // 512 blocks
    dim3 block(NTHREADS);

    pass1_chunk_sums<<<grid, block>>>(x);
    pass2_scan<<<grid, block>>>(x, out);
}